// round 15
// baseline (speedup 1.0000x reference)
#include <cuda_runtime.h>
#include <math.h>

// Problem constants (fixed by the dataset)
#define EN 800000
#define QN 50000
#define DD 128
#define NB_SCAN ((QN + 1023) / 1024)   // 49
#define NEG_BIG (-1.0e30f)

// -------- scratch (__device__ globals; no allocation allowed) --------
__device__ __align__(16) float g_M[DD * DD];     // Wq @ Wk^T
__device__ __align__(16) float g_r[DD];          // Wk @ bq
__device__ __align__(16) float g_v[DD];          // Wq @ bk
__device__ float g_s0;                            // bk . bq
__device__ __align__(16) float g_z[QN * DD];     // (queries @ M + r) * scale
__device__ float g_c[QN];                        // (queries . v + s0) * scale
__device__ int   g_eid[EN];                      // segment-sorted edge ids
__device__ int   g_pos[EN];                      // rank of edge within its segment
__device__ int   g_count[QN];
__device__ int   g_start[QN + 1];
__device__ int   g_blocksum[64];

// -------- histogram of indices + per-edge rank --------
__global__ void k_hist(const int* __restrict__ idx) {
    int i = blockIdx.x * blockDim.x + threadIdx.x;
    int n = gridDim.x * blockDim.x;
    const int4* idx4 = (const int4*)idx;
    for (int e4 = i; e4 < EN / 4; e4 += n) {
        int4 v = idx4[e4];
        int e = e4 * 4;
        g_pos[e + 0] = atomicAdd(&g_count[v.x], 1);
        g_pos[e + 1] = atomicAdd(&g_count[v.y], 1);
        g_pos[e + 2] = atomicAdd(&g_count[v.z], 1);
        g_pos[e + 3] = atomicAdd(&g_count[v.w], 1);
    }
}

// -------- precompute folded weights: M, r, v, s0 --------
__global__ void k_pre(const float* __restrict__ Wq, const float* __restrict__ bq,
                      const float* __restrict__ Wk, const float* __restrict__ bk) {
    if (blockIdx.x == 64) {
        int t = threadIdx.x;
        if (t < DD) {
            float rr = 0.f, vv = 0.f;
            for (int j = 0; j < DD; j++) {
                rr += Wk[t * DD + j] * bq[j];
                vv += Wq[t * DD + j] * bk[j];
            }
            g_r[t] = rr;
            g_v[t] = vv;
            if (t == 0) {
                float s = 0.f;
                for (int j = 0; j < DD; j++) s += bk[j] * bq[j];
                g_s0 = s;
            }
        }
        return;
    }
    int o = blockIdx.x * 256 + threadIdx.x;   // 0..16383
    int t = o >> 7;          // row of Wq
    int i = o & 127;         // row of Wk
    float acc = 0.f;
    for (int j = 0; j < DD; j++) acc += Wq[t * DD + j] * Wk[i * DD + j];
    g_M[t * DD + i] = acc;
}

// -------- z = (queries @ M + r)*scale ; c = (queries . v + s0)*scale --------
// 128x128 block tile, 256 threads, 8x8 register tile, KC=16.
#define ZT 128
#define ZKC 16
__global__ void __launch_bounds__(256) k_z(const float* __restrict__ queries) {
    __shared__ float sQ[ZKC][ZT];     // transposed: sQ[k][row]
    __shared__ float sM[ZKC][DD];
    __shared__ float sV[ZKC];
    int tid = threadIdx.x;
    int tx = tid & 15;                // output-col group (8 cols)
    int ty = tid >> 4;                // row group (8 rows)
    int q0 = blockIdx.x * ZT;

    float acc[8][8];
#pragma unroll
    for (int i = 0; i < 8; i++)
#pragma unroll
        for (int jj = 0; jj < 8; jj++) acc[i][jj] = 0.f;
    float cacc[8] = {0.f, 0.f, 0.f, 0.f, 0.f, 0.f, 0.f, 0.f};

    for (int kc = 0; kc < DD; kc += ZKC) {
        __syncthreads();
        // stage queries tile 128 rows x 16 k (transposed into sQ)
#pragma unroll
        for (int r = 0; r < 2; r++) {
            int fidx = r * 256 + tid;     // 0..511
            int row = fidx >> 2;          // 0..127
            int c4 = fidx & 3;            // 0..3
            float4 f = make_float4(0.f, 0.f, 0.f, 0.f);
            if (q0 + row < QN)
                f = *(const float4*)&queries[(q0 + row) * DD + kc + c4 * 4];
            sQ[c4 * 4 + 0][row] = f.x;
            sQ[c4 * 4 + 1][row] = f.y;
            sQ[c4 * 4 + 2][row] = f.z;
            sQ[c4 * 4 + 3][row] = f.w;
        }
        // stage M tile 16 k-rows x 128 cols
#pragma unroll
        for (int r = 0; r < 2; r++) {
            int fidx = r * 256 + tid;     // 0..511
            int row = fidx >> 5;          // 0..15
            int c4 = fidx & 31;           // 0..31
            *(float4*)&sM[row][c4 * 4] = *(const float4*)&g_M[(kc + row) * DD + c4 * 4];
        }
        if (tid < ZKC) sV[tid] = g_v[kc + tid];
        __syncthreads();

#pragma unroll
        for (int kk = 0; kk < ZKC; kk++) {
            float4 a0 = *(float4*)&sQ[kk][ty * 8];
            float4 a1 = *(float4*)&sQ[kk][ty * 8 + 4];
            float4 b0 = *(float4*)&sM[kk][tx * 8];
            float4 b1 = *(float4*)&sM[kk][tx * 8 + 4];
            float vv = sV[kk];
            float av[8] = {a0.x, a0.y, a0.z, a0.w, a1.x, a1.y, a1.z, a1.w};
            float bv[8] = {b0.x, b0.y, b0.z, b0.w, b1.x, b1.y, b1.z, b1.w};
#pragma unroll
            for (int i = 0; i < 8; i++) {
#pragma unroll
                for (int jj = 0; jj < 8; jj++) acc[i][jj] += av[i] * bv[jj];
                cacc[i] += av[i] * vv;
            }
        }
    }

    const float scale = 0.0883883476483184f;  // 128^-0.5
    int n0 = tx * 8;
    float4 r0 = *(const float4*)&g_r[n0];
    float4 r1 = *(const float4*)&g_r[n0 + 4];
    float s0v = g_s0;
#pragma unroll
    for (int i = 0; i < 8; i++) {
        int q = q0 + ty * 8 + i;
        if (q < QN) {
            float4 o0 = make_float4((acc[i][0] + r0.x) * scale, (acc[i][1] + r0.y) * scale,
                                    (acc[i][2] + r0.z) * scale, (acc[i][3] + r0.w) * scale);
            float4 o1 = make_float4((acc[i][4] + r1.x) * scale, (acc[i][5] + r1.y) * scale,
                                    (acc[i][6] + r1.z) * scale, (acc[i][7] + r1.w) * scale);
            *(float4*)&g_z[q * DD + n0] = o0;
            *(float4*)&g_z[q * DD + n0 + 4] = o1;
            if (tx == 0) g_c[q] = (cacc[i] + s0v) * scale;
        }
    }
}

// -------- scan: per-block exclusive scan + aggregates --------
__global__ void k_scan1() {
    __shared__ int s[1024];
    int tid = threadIdx.x;
    int g = blockIdx.x * 1024 + tid;
    int val = (g < QN) ? g_count[g] : 0;
    s[tid] = val;
    __syncthreads();
    for (int off = 1; off < 1024; off <<= 1) {
        int t = (tid >= off) ? s[tid - off] : 0;
        __syncthreads();
        s[tid] += t;
        __syncthreads();
    }
    if (g < QN) g_start[g] = s[tid] - val;
    if (tid == 1023) g_blocksum[blockIdx.x] = s[1023];
}

// -------- scan fixup: every block prefix-sums the 49 aggregates in smem --------
__global__ void k_scan2() {
    __shared__ int sB[64];
    int tid = threadIdx.x;
    if (tid < 64) sB[tid] = (tid < NB_SCAN) ? g_blocksum[tid] : 0;
    __syncthreads();
    for (int off = 1; off < 64; off <<= 1) {
        int t = (tid < 64 && tid >= off) ? sB[tid - off] : 0;
        __syncthreads();
        if (tid < 64) sB[tid] += t;
        __syncthreads();
    }
    int base = (blockIdx.x == 0) ? 0 : sB[blockIdx.x - 1];
    int g = blockIdx.x * 1024 + tid;
    if (g < QN) g_start[g] += base;
    if (g == 0) g_start[QN] = EN;
}

// -------- atomic-free fill: eid[start[q] + pos[e]] = e --------
__global__ void k_fill(const int* __restrict__ idx) {
    int e = blockIdx.x * blockDim.x + threadIdx.x;
    if (e < EN) {
        int q = idx[e];
        g_eid[g_start[q] + g_pos[e]] = e;
    }
}

// -------- fused: probs + online softmax + weighted gather-sum --------
// Persistent grid-stride warps, one segment per iteration, segment metadata
// (start pair / eid / z-row / c) software-pipelined TWO segments deep so the
// serial LDG start -> LDG eid -> LDG SV chain is hidden behind the previous
// segment's compute. Loop body is branch-free; the first two 8-edge groups
// (covering cnt<=16, ~57% of segments) execute unconditionally so their 16
// SV loads front-batch.

#define GROUP8(base)                                                           \
    {                                                                          \
        int lim = rem - 1;                                                     \
        int e0 = __shfl_sync(0xffffffffu, eid_l, min((base) + 0, lim));        \
        int e1 = __shfl_sync(0xffffffffu, eid_l, min((base) + 1, lim));        \
        int e2 = __shfl_sync(0xffffffffu, eid_l, min((base) + 2, lim));        \
        int e3 = __shfl_sync(0xffffffffu, eid_l, min((base) + 3, lim));        \
        int e4 = __shfl_sync(0xffffffffu, eid_l, min((base) + 4, lim));        \
        int e5 = __shfl_sync(0xffffffffu, eid_l, min((base) + 5, lim));        \
        int e6 = __shfl_sync(0xffffffffu, eid_l, min((base) + 6, lim));        \
        int e7 = __shfl_sync(0xffffffffu, eid_l, min((base) + 7, lim));        \
        float4 a0 = sv4[e0 * 32 + lane];                                       \
        float4 a1 = sv4[e1 * 32 + lane];                                       \
        float4 a2 = sv4[e2 * 32 + lane];                                       \
        float4 a3 = sv4[e3 * 32 + lane];                                       \
        float4 a4 = sv4[e4 * 32 + lane];                                       \
        float4 a5 = sv4[e5 * 32 + lane];                                       \
        float4 a6 = sv4[e6 * 32 + lane];                                       \
        float4 a7 = sv4[e7 * 32 + lane];                                       \
        float d0 = a0.x * zr.x + a0.y * zr.y + a0.z * zr.z + a0.w * zr.w;      \
        float d1 = a1.x * zr.x + a1.y * zr.y + a1.z * zr.z + a1.w * zr.w;      \
        float d2 = a2.x * zr.x + a2.y * zr.y + a2.z * zr.z + a2.w * zr.w;      \
        float d3 = a3.x * zr.x + a3.y * zr.y + a3.z * zr.z + a3.w * zr.w;      \
        float d4 = a4.x * zr.x + a4.y * zr.y + a4.z * zr.z + a4.w * zr.w;      \
        float d5 = a5.x * zr.x + a5.y * zr.y + a5.z * zr.z + a5.w * zr.w;      \
        float d6 = a6.x * zr.x + a6.y * zr.y + a6.z * zr.z + a6.w * zr.w;      \
        float d7 = a7.x * zr.x + a7.y * zr.y + a7.z * zr.z + a7.w * zr.w;      \
        _Pragma("unroll")                                                      \
        for (int off = 16; off >= 1; off >>= 1) {                              \
            d0 += __shfl_xor_sync(0xffffffffu, d0, off);                       \
            d1 += __shfl_xor_sync(0xffffffffu, d1, off);                       \
            d2 += __shfl_xor_sync(0xffffffffu, d2, off);                       \
            d3 += __shfl_xor_sync(0xffffffffu, d3, off);                       \
            d4 += __shfl_xor_sync(0xffffffffu, d4, off);                       \
            d5 += __shfl_xor_sync(0xffffffffu, d5, off);                       \
            d6 += __shfl_xor_sync(0xffffffffu, d6, off);                       \
            d7 += __shfl_xor_sync(0xffffffffu, d7, off);                       \
        }                                                                      \
        float p0 = ((base) + 0 < rem) ? d0 + cq : NEG_BIG;                     \
        float p1 = ((base) + 1 < rem) ? d1 + cq : NEG_BIG;                     \
        float p2 = ((base) + 2 < rem) ? d2 + cq : NEG_BIG;                     \
        float p3 = ((base) + 3 < rem) ? d3 + cq : NEG_BIG;                     \
        float p4 = ((base) + 4 < rem) ? d4 + cq : NEG_BIG;                     \
        float p5 = ((base) + 5 < rem) ? d5 + cq : NEG_BIG;                     \
        float p6 = ((base) + 6 < rem) ? d6 + cq : NEG_BIG;                     \
        float p7 = ((base) + 7 < rem) ? d7 + cq : NEG_BIG;                     \
        plocal = (lane == (base) + 0) ? p0 : plocal;                           \
        plocal = (lane == (base) + 1) ? p1 : plocal;                           \
        plocal = (lane == (base) + 2) ? p2 : plocal;                           \
        plocal = (lane == (base) + 3) ? p3 : plocal;                           \
        plocal = (lane == (base) + 4) ? p4 : plocal;                           \
        plocal = (lane == (base) + 5) ? p5 : plocal;                           \
        plocal = (lane == (base) + 6) ? p6 : plocal;                           \
        plocal = (lane == (base) + 7) ? p7 : plocal;                           \
        float gm = fmaxf(fmaxf(fmaxf(p0, p1), fmaxf(p2, p3)),                  \
                         fmaxf(fmaxf(p4, p5), fmaxf(p6, p7)));                 \
        float M2 = fmaxf(m, gm);                                               \
        float f = __expf(m - M2);   /* m=-inf first time -> f=0 */             \
        m = M2;                                                                \
        float w0 = __expf(p0 - M2), w1 = __expf(p1 - M2);                      \
        float w2 = __expf(p2 - M2), w3 = __expf(p3 - M2);                      \
        float w4 = __expf(p4 - M2), w5 = __expf(p5 - M2);                      \
        float w6 = __expf(p6 - M2), w7 = __expf(p7 - M2);                      \
        ssum = ssum * f + (((w0 + w1) + (w2 + w3)) + ((w4 + w5) + (w6 + w7))); \
        acc.x = acc.x * f + w0 * a0.x + w1 * a1.x + w2 * a2.x + w3 * a3.x      \
                          + w4 * a4.x + w5 * a5.x + w6 * a6.x + w7 * a7.x;     \
        acc.y = acc.y * f + w0 * a0.y + w1 * a1.y + w2 * a2.y + w3 * a3.y      \
                          + w4 * a4.y + w5 * a5.y + w6 * a6.y + w7 * a7.y;     \
        acc.z = acc.z * f + w0 * a0.z + w1 * a1.z + w2 * a2.z + w3 * a3.z      \
                          + w4 * a4.z + w5 * a5.z + w6 * a6.z + w7 * a7.z;     \
        acc.w = acc.w * f + w0 * a0.w + w1 * a1.w + w2 * a2.w + w3 * a3.w      \
                          + w4 * a4.w + w5 * a5.w + w6 * a6.w + w7 * a7.w;     \
    }

#define FUSED_GRID 296

__global__ void __launch_bounds__(256) k_fused(const float* __restrict__ sv,
                                               float* __restrict__ scores,
                                               float* __restrict__ attn) {
    int lane = threadIdx.x & 31;
    int gw = (blockIdx.x * blockDim.x + threadIdx.x) >> 5;
    const int nw = (FUSED_GRID * 256) >> 5;   // 2368 warps
    const float4* sv4 = (const float4*)sv;
    const float4* z4 = (const float4*)g_z;

    int q = gw;
    if (q >= QN) return;

    // ---- pipeline prologue ----
    // current segment (q)
    int s0 = g_start[q];
    int s1 = g_start[q + 1];
    int cnt = s1 - s0;
    int eid_l = g_eid[min(s0 + ((cnt > 0) ? min(lane, cnt - 1) : 0), EN - 1)];
    float4 zr = z4[q * 32 + lane];
    float cq = g_c[q];
    // next segment (q + nw): start pair only
    int qn = q + nw;
    int s0n = 0, s1n = 0;
    if (qn < QN) { s0n = g_start[qn]; s1n = g_start[qn + 1]; }

    while (true) {
        // issue next segment's eid/z/c loads NOW (addresses ready from s0n),
        // and the start pair for the segment after that — both overlap with
        // the current segment's compute below.
        int cntn = s1n - s0n;
        int eid_n = 0; float4 zrn = make_float4(0.f, 0.f, 0.f, 0.f); float cqn = 0.f;
        if (qn < QN) {
            eid_n = g_eid[min(s0n + ((cntn > 0) ? min(lane, cntn - 1) : 0), EN - 1)];
            zrn = z4[qn * 32 + lane];
            cqn = g_c[qn];
        }
        int qnn = qn + nw;
        int s0nn = 0, s1nn = 0;
        if (qnn < QN) { s0nn = g_start[qnn]; s1nn = g_start[qnn + 1]; }

        // ---- process current segment ----
        float m = -INFINITY;
        float ssum = 0.f;
        float4 acc = make_float4(0.f, 0.f, 0.f, 0.f);

        if (cnt > 0 && cnt <= 32) {
            int rem = cnt;
            float plocal = NEG_BIG;
            GROUP8(0);
            GROUP8(8);
            if (cnt > 16) { GROUP8(16); GROUP8(24); }
            float inv = 1.0f / ssum;
            if (lane < cnt) scores[eid_l] = __expf(plocal - m) * inv;
            ((float4*)attn)[q * 32 + lane] =
                make_float4(acc.x * inv, acc.y * inv, acc.z * inv, acc.w * inv);
        } else if (cnt <= 0) {
            ((float4*)attn)[q * 32 + lane] = make_float4(0.f, 0.f, 0.f, 0.f);
        } else {
            // ---- generic path (rare: P(cnt>32) ~ 2e-4): chunked, two-pass ----
            for (int base = s0; base < s1; base += 32) {
                int rem = s1 - base; if (rem > 32) rem = 32;
                int eid_c = g_eid[base + ((lane < rem) ? lane : rem - 1)];
                float plocal = NEG_BIG;   // unused here
                {
                    int eid_sav = eid_l; eid_l = eid_c;
                    int ngrp = (rem + 7) >> 3;
                    if (ngrp > 0) GROUP8(0);
                    if (ngrp > 1) GROUP8(8);
                    if (ngrp > 2) GROUP8(16);
                    if (ngrp > 3) GROUP8(24);
                    eid_l = eid_sav;
                }
                (void)plocal;
            }
            float inv2 = 1.0f / ssum;
            for (int base = s0; base < s1; base += 32) {
                int rem = s1 - base; if (rem > 32) rem = 32;
                int eid_c = g_eid[base + ((lane < rem) ? lane : rem - 1)];
                float sc = 0.f;
#pragma unroll 1
                for (int k = 0; k < 32; k++) {
                    if (k >= rem) break;
                    int e = __shfl_sync(0xffffffffu, eid_c, k);
                    float4 a = sv4[e * 32 + lane];
                    float d = a.x * zr.x + a.y * zr.y + a.z * zr.z + a.w * zr.w;
#pragma unroll
                    for (int off = 16; off >= 1; off >>= 1)
                        d += __shfl_xor_sync(0xffffffffu, d, off);
                    sc = (lane == k) ? __expf(d + cq - m) * inv2 : sc;
                }
                if (lane < rem) scores[eid_c] = sc;
            }
            ((float4*)attn)[q * 32 + lane] =
                make_float4(acc.x * inv2, acc.y * inv2, acc.z * inv2, acc.w * inv2);
        }

        // ---- rotate pipeline ----
        if (qn >= QN) break;
        q = qn; s0 = s0n; s1 = s1n; cnt = cntn;
        eid_l = eid_n; zr = zrn; cq = cqn;
        qn = qnn; s0n = s0nn; s1n = s1nn;
    }
}

// -------- launcher --------
// inputs (metadata order): scattered_values [E,D] f32, indices [E] i32,
// queries [Q,D] f32, Wq [D,D], bq [D], Wk [D,D], bk [D]
// output: scores [E] then attn_applied [Q,D], fp32, concatenated.
extern "C" void kernel_launch(void* const* d_in, const int* in_sizes, int n_in,
                              void* d_out, int out_size) {
    const float* sv      = (const float*)d_in[0];
    const int*   idx     = (const int*)d_in[1];
    const float* queries = (const float*)d_in[2];
    const float* Wq      = (const float*)d_in[3];
    const float* bq      = (const float*)d_in[4];
    const float* Wk      = (const float*)d_in[5];
    const float* bk      = (const float*)d_in[6];
    float* scores = (float*)d_out;
    float* attn   = (float*)d_out + EN;

    // side stream + events + symbol address (created once, outside any capture;
    // every call performs identical work)
    static cudaStream_t s2 = nullptr;
    static cudaEvent_t evFork = nullptr, evJoin = nullptr;
    static void* countPtr = nullptr;
    if (s2 == nullptr) {
        cudaStreamCreateWithFlags(&s2, cudaStreamNonBlocking);
        cudaEventCreateWithFlags(&evFork, cudaEventDisableTiming);
        cudaEventCreateWithFlags(&evJoin, cudaEventDisableTiming);
        cudaGetSymbolAddress(&countPtr, g_count);
    }

    // fork: CSR-build chain on s2, GEMM chain on the main stream
    cudaEventRecord(evFork, 0);
    cudaStreamWaitEvent(s2, evFork, 0);

    cudaMemsetAsync(countPtr, 0, QN * sizeof(int), s2);
    k_hist<<<784, 256, 0, s2>>>(idx);
    k_scan1<<<NB_SCAN, 1024, 0, s2>>>();
    k_scan2<<<NB_SCAN, 1024, 0, s2>>>();
    k_fill<<<(EN + 255) / 256, 256, 0, s2>>>(idx);
    cudaEventRecord(evJoin, s2);

    k_pre<<<65, 256>>>(Wq, bq, Wk, bk);
    k_z<<<(QN + ZT - 1) / ZT, 256>>>(queries);

    // join, then the fused pass
    cudaStreamWaitEvent(0, evJoin, 0);
    k_fused<<<FUSED_GRID, 256>>>(sv, scores, attn);
}

// round 16
// speedup vs baseline: 1.4344x; 1.4344x over previous
#include <cuda_runtime.h>
#include <math.h>

// Problem constants (fixed by the dataset)
#define EN 800000
#define QN 50000
#define DD 128
#define NB_SCAN ((QN + 1023) / 1024)   // 49
#define CAP 160                        // per-warp prob cache (segments > CAP use slow path)
#define QSPLIT 25088                   // chunk boundary (multiple of 128)

// -------- scratch (__device__ globals; no allocation allowed) --------
__device__ __align__(16) float g_M[DD * DD];     // Wq @ Wk^T
__device__ __align__(16) float g_r[DD];          // Wk @ bq
__device__ __align__(16) float g_v[DD];          // Wq @ bk
__device__ float g_s0;                            // bk . bq
__device__ __align__(16) float g_z[QN * DD];     // (queries @ M + r) * scale
__device__ float g_c[QN];                        // (queries . v + s0) * scale
__device__ int   g_eid[EN];                      // segment-sorted edge ids
__device__ int   g_pos[EN];                      // rank of edge within its segment
__device__ int   g_count[QN];
__device__ int   g_start[QN + 1];
__device__ int   g_blocksum[64];

// -------- histogram of indices + per-edge rank --------
__global__ void k_hist(const int* __restrict__ idx) {
    int i = blockIdx.x * blockDim.x + threadIdx.x;
    int n = gridDim.x * blockDim.x;
    const int4* idx4 = (const int4*)idx;
    for (int e4 = i; e4 < EN / 4; e4 += n) {
        int4 v = idx4[e4];
        int e = e4 * 4;
        g_pos[e + 0] = atomicAdd(&g_count[v.x], 1);
        g_pos[e + 1] = atomicAdd(&g_count[v.y], 1);
        g_pos[e + 2] = atomicAdd(&g_count[v.z], 1);
        g_pos[e + 3] = atomicAdd(&g_count[v.w], 1);
    }
}

// -------- precompute folded weights: M, r, v, s0 --------
__global__ void k_pre(const float* __restrict__ Wq, const float* __restrict__ bq,
                      const float* __restrict__ Wk, const float* __restrict__ bk) {
    if (blockIdx.x == 64) {
        int t = threadIdx.x;
        if (t < DD) {
            float rr = 0.f, vv = 0.f;
            for (int j = 0; j < DD; j++) {
                rr += Wk[t * DD + j] * bq[j];
                vv += Wq[t * DD + j] * bk[j];
            }
            g_r[t] = rr;
            g_v[t] = vv;
            if (t == 0) {
                float s = 0.f;
                for (int j = 0; j < DD; j++) s += bk[j] * bq[j];
                g_s0 = s;
            }
        }
        return;
    }
    int o = blockIdx.x * 256 + threadIdx.x;   // 0..16383
    int t = o >> 7;          // row of Wq
    int i = o & 127;         // row of Wk
    float acc = 0.f;
    for (int j = 0; j < DD; j++) acc += Wq[t * DD + j] * Wk[i * DD + j];
    g_M[t * DD + i] = acc;
}

// -------- z = (queries @ M + r)*scale ; c = (queries . v + s0)*scale --------
// 128x128 block tile, 256 threads, 8x8 register tile, KC=16; chunked by qbase.
#define ZT 128
#define ZKC 16
__global__ void __launch_bounds__(256) k_z(const float* __restrict__ queries, int qbase) {
    __shared__ float sQ[ZKC][ZT];     // transposed: sQ[k][row]
    __shared__ float sM[ZKC][DD];
    __shared__ float sV[ZKC];
    int tid = threadIdx.x;
    int tx = tid & 15;                // output-col group (8 cols)
    int ty = tid >> 4;                // row group (8 rows)
    int q0 = qbase + blockIdx.x * ZT;

    float acc[8][8];
#pragma unroll
    for (int i = 0; i < 8; i++)
#pragma unroll
        for (int jj = 0; jj < 8; jj++) acc[i][jj] = 0.f;
    float cacc[8] = {0.f, 0.f, 0.f, 0.f, 0.f, 0.f, 0.f, 0.f};

    for (int kc = 0; kc < DD; kc += ZKC) {
        __syncthreads();
        // stage queries tile 128 rows x 16 k (transposed into sQ)
#pragma unroll
        for (int r = 0; r < 2; r++) {
            int fidx = r * 256 + tid;     // 0..511
            int row = fidx >> 2;          // 0..127
            int c4 = fidx & 3;            // 0..3
            float4 f = make_float4(0.f, 0.f, 0.f, 0.f);
            if (q0 + row < QN)
                f = *(const float4*)&queries[(q0 + row) * DD + kc + c4 * 4];
            sQ[c4 * 4 + 0][row] = f.x;
            sQ[c4 * 4 + 1][row] = f.y;
            sQ[c4 * 4 + 2][row] = f.z;
            sQ[c4 * 4 + 3][row] = f.w;
        }
        // stage M tile 16 k-rows x 128 cols
#pragma unroll
        for (int r = 0; r < 2; r++) {
            int fidx = r * 256 + tid;     // 0..511
            int row = fidx >> 5;          // 0..15
            int c4 = fidx & 31;           // 0..31
            *(float4*)&sM[row][c4 * 4] = *(const float4*)&g_M[(kc + row) * DD + c4 * 4];
        }
        if (tid < ZKC) sV[tid] = g_v[kc + tid];
        __syncthreads();

#pragma unroll
        for (int kk = 0; kk < ZKC; kk++) {
            float4 a0 = *(float4*)&sQ[kk][ty * 8];
            float4 a1 = *(float4*)&sQ[kk][ty * 8 + 4];
            float4 b0 = *(float4*)&sM[kk][tx * 8];
            float4 b1 = *(float4*)&sM[kk][tx * 8 + 4];
            float vv = sV[kk];
            float av[8] = {a0.x, a0.y, a0.z, a0.w, a1.x, a1.y, a1.z, a1.w};
            float bv[8] = {b0.x, b0.y, b0.z, b0.w, b1.x, b1.y, b1.z, b1.w};
#pragma unroll
            for (int i = 0; i < 8; i++) {
#pragma unroll
                for (int jj = 0; jj < 8; jj++) acc[i][jj] += av[i] * bv[jj];
                cacc[i] += av[i] * vv;
            }
        }
    }

    const float scale = 0.0883883476483184f;  // 128^-0.5
    int n0 = tx * 8;
    float4 r0 = *(const float4*)&g_r[n0];
    float4 r1 = *(const float4*)&g_r[n0 + 4];
    float s0v = g_s0;
#pragma unroll
    for (int i = 0; i < 8; i++) {
        int q = q0 + ty * 8 + i;
        if (q < QN) {
            float4 o0 = make_float4((acc[i][0] + r0.x) * scale, (acc[i][1] + r0.y) * scale,
                                    (acc[i][2] + r0.z) * scale, (acc[i][3] + r0.w) * scale);
            float4 o1 = make_float4((acc[i][4] + r1.x) * scale, (acc[i][5] + r1.y) * scale,
                                    (acc[i][6] + r1.z) * scale, (acc[i][7] + r1.w) * scale);
            *(float4*)&g_z[q * DD + n0] = o0;
            *(float4*)&g_z[q * DD + n0 + 4] = o1;
            if (tx == 0) g_c[q] = (cacc[i] + s0v) * scale;
        }
    }
}

// -------- scan: per-block exclusive scan + aggregates --------
__global__ void k_scan1() {
    __shared__ int s[1024];
    int tid = threadIdx.x;
    int g = blockIdx.x * 1024 + tid;
    int val = (g < QN) ? g_count[g] : 0;
    s[tid] = val;
    __syncthreads();
    for (int off = 1; off < 1024; off <<= 1) {
        int t = (tid >= off) ? s[tid - off] : 0;
        __syncthreads();
        s[tid] += t;
        __syncthreads();
    }
    if (g < QN) g_start[g] = s[tid] - val;
    if (tid == 1023) g_blocksum[blockIdx.x] = s[1023];
}

// -------- scan fixup: every block prefix-sums the 49 aggregates in smem --------
__global__ void k_scan2() {
    __shared__ int sB[64];
    int tid = threadIdx.x;
    if (tid < 64) sB[tid] = (tid < NB_SCAN) ? g_blocksum[tid] : 0;
    __syncthreads();
    for (int off = 1; off < 64; off <<= 1) {
        int t = (tid < 64 && tid >= off) ? sB[tid - off] : 0;
        __syncthreads();
        if (tid < 64) sB[tid] += t;
        __syncthreads();
    }
    int base = (blockIdx.x == 0) ? 0 : sB[blockIdx.x - 1];
    int g = blockIdx.x * 1024 + tid;
    if (g < QN) g_start[g] += base;
    if (g == 0) g_start[QN] = EN;
}

// -------- atomic-free fill: eid[start[q] + pos[e]] = e --------
__global__ void k_fill(const int* __restrict__ idx) {
    int e = blockIdx.x * blockDim.x + threadIdx.x;
    if (e < EN) {
        int q = idx[e];
        g_eid[g_start[q] + g_pos[e]] = e;
    }
}

// -------- fused single pass: probs + online softmax + weighted gather-sum --------
// (the measured-best R5 form: 4-wide pipeline + scalar tail, warp per segment)
__device__ __forceinline__ float warp_red_sum(float d) {
#pragma unroll
    for (int off = 16; off >= 1; off >>= 1)
        d += __shfl_xor_sync(0xffffffffu, d, off);
    return d;
}

__global__ void __launch_bounds__(256) k_fused(const float* __restrict__ sv,
                                               float* __restrict__ scores,
                                               float* __restrict__ attn,
                                               int qbase) {
    __shared__ float sP[8][CAP];
    int w = threadIdx.x >> 5;
    int lane = threadIdx.x & 31;
    int q = qbase + blockIdx.x * 8 + w;
    if (q >= QN) return;

    const float4* sv4 = (const float4*)sv;
    int s0 = g_start[q];
    int s1 = g_start[q + 1];
    int cnt = s1 - s0;

    // z row (pre-scaled) + c for this segment (coalesced: q is block-sequential)
    float4 zr = ((const float4*)g_z)[q * 32 + lane];
    float cq = g_c[q];

    // ---- single pass: probs + online (m, ssum, acc) ----
    float m = -INFINITY;
    float ssum = 0.f;
    float4 acc = make_float4(0.f, 0.f, 0.f, 0.f);

    int j = s0;
    for (; j + 3 < s1; j += 4) {
        int e0 = g_eid[j], e1 = g_eid[j + 1], e2 = g_eid[j + 2], e3 = g_eid[j + 3];
        float4 a0 = sv4[e0 * 32 + lane];
        float4 a1 = sv4[e1 * 32 + lane];
        float4 a2 = sv4[e2 * 32 + lane];
        float4 a3 = sv4[e3 * 32 + lane];
        float d0 = a0.x * zr.x + a0.y * zr.y + a0.z * zr.z + a0.w * zr.w;
        float d1 = a1.x * zr.x + a1.y * zr.y + a1.z * zr.z + a1.w * zr.w;
        float d2 = a2.x * zr.x + a2.y * zr.y + a2.z * zr.z + a2.w * zr.w;
        float d3 = a3.x * zr.x + a3.y * zr.y + a3.z * zr.z + a3.w * zr.w;
#pragma unroll
        for (int off = 16; off >= 1; off >>= 1) {
            d0 += __shfl_xor_sync(0xffffffffu, d0, off);
            d1 += __shfl_xor_sync(0xffffffffu, d1, off);
            d2 += __shfl_xor_sync(0xffffffffu, d2, off);
            d3 += __shfl_xor_sync(0xffffffffu, d3, off);
        }
        float p0 = d0 + cq, p1 = d1 + cq, p2 = d2 + cq, p3 = d3 + cq;
        int o = j - s0;
        if (o + 4 <= CAP && lane < 4) {
            float pk = (lane == 0) ? p0 : (lane == 1) ? p1 : (lane == 2) ? p2 : p3;
            sP[w][o + lane] = pk;
        }
        float gm = fmaxf(fmaxf(p0, p1), fmaxf(p2, p3));
        if (gm > m) {   // warp-uniform branch
            float f = __expf(m - gm);
            ssum *= f;
            acc.x *= f; acc.y *= f; acc.z *= f; acc.w *= f;
            m = gm;
        }
        float w0 = __expf(p0 - m), w1 = __expf(p1 - m);
        float w2 = __expf(p2 - m), w3 = __expf(p3 - m);
        ssum += (w0 + w1) + (w2 + w3);
        acc.x += w0 * a0.x + w1 * a1.x + w2 * a2.x + w3 * a3.x;
        acc.y += w0 * a0.y + w1 * a1.y + w2 * a2.y + w3 * a3.y;
        acc.z += w0 * a0.z + w1 * a1.z + w2 * a2.z + w3 * a3.z;
        acc.w += w0 * a0.w + w1 * a1.w + w2 * a2.w + w3 * a3.w;
    }
    for (; j < s1; j++) {
        int e = g_eid[j];
        float4 a = sv4[e * 32 + lane];
        float d = warp_red_sum(a.x * zr.x + a.y * zr.y + a.z * zr.z + a.w * zr.w);
        float p = d + cq;
        int o = j - s0;
        if (o < CAP && lane == 0) sP[w][o] = p;
        if (p > m) {
            float f = __expf(m - p);
            ssum *= f;
            acc.x *= f; acc.y *= f; acc.z *= f; acc.w *= f;
            m = p;
        }
        float w0 = __expf(p - m);
        ssum += w0;
        acc.x += w0 * a.x; acc.y += w0 * a.y; acc.z += w0 * a.z; acc.w += w0 * a.w;
    }
    __syncwarp();

    float inv = (cnt > 0) ? (1.0f / ssum) : 0.f;

    // ---- epilogue: scores from cached probs ----
    int stored = cnt < CAP ? cnt : CAP;
    for (int t = lane; t < stored; t += 32)
        scores[g_eid[s0 + t]] = __expf(sP[w][t] - m) * inv;
    // rare overflow path: recompute dot for edges beyond CAP
    for (int jo = s0 + CAP; jo < s1; jo++) {
        int e = g_eid[jo];
        float4 a = sv4[e * 32 + lane];
        float d = warp_red_sum(a.x * zr.x + a.y * zr.y + a.z * zr.z + a.w * zr.w);
        if (lane == 0) scores[e] = __expf(d + cq - m) * inv;
    }

    ((float4*)attn)[q * 32 + lane] =
        make_float4(acc.x * inv, acc.y * inv, acc.z * inv, acc.w * inv);
}

// -------- launcher --------
// inputs (metadata order): scattered_values [E,D] f32, indices [E] i32,
// queries [Q,D] f32, Wq [D,D], bq [D], Wk [D,D], bk [D]
// output: scores [E] then attn_applied [Q,D], fp32, concatenated.
//
// Schedule (software pipeline across streams):
//   s2  : memset -> hist -> scan1 -> scan2 -> fill            -> evJoin
//   main: pre -> kz(chunk0) -> evZ0 -> kz(chunk1)
//   s3  : wait(evZ0, evJoin) -> fused(chunk0) -> evF0          (overlaps kz1)
//   main: wait(evJoin) -> fused(chunk1) -> wait(evF0)
extern "C" void kernel_launch(void* const* d_in, const int* in_sizes, int n_in,
                              void* d_out, int out_size) {
    const float* sv      = (const float*)d_in[0];
    const int*   idx     = (const int*)d_in[1];
    const float* queries = (const float*)d_in[2];
    const float* Wq      = (const float*)d_in[3];
    const float* bq      = (const float*)d_in[4];
    const float* Wk      = (const float*)d_in[5];
    const float* bk      = (const float*)d_in[6];
    float* scores = (float*)d_out;
    float* attn   = (float*)d_out + EN;

    static cudaStream_t s2 = nullptr, s3 = nullptr;
    static cudaEvent_t evFork = nullptr, evJoin = nullptr, evZ0 = nullptr, evF0 = nullptr;
    static void* countPtr = nullptr;
    if (s2 == nullptr) {
        cudaStreamCreateWithFlags(&s2, cudaStreamNonBlocking);
        cudaStreamCreateWithFlags(&s3, cudaStreamNonBlocking);
        cudaEventCreateWithFlags(&evFork, cudaEventDisableTiming);
        cudaEventCreateWithFlags(&evJoin, cudaEventDisableTiming);
        cudaEventCreateWithFlags(&evZ0, cudaEventDisableTiming);
        cudaEventCreateWithFlags(&evF0, cudaEventDisableTiming);
        cudaGetSymbolAddress(&countPtr, g_count);
    }

    // fork
    cudaEventRecord(evFork, 0);
    cudaStreamWaitEvent(s2, evFork, 0);

    // CSR arm on s2
    cudaMemsetAsync(countPtr, 0, QN * sizeof(int), s2);
    k_hist<<<784, 256, 0, s2>>>(idx);
    k_scan1<<<NB_SCAN, 1024, 0, s2>>>();
    k_scan2<<<NB_SCAN, 1024, 0, s2>>>();
    k_fill<<<(EN + 255) / 256, 256, 0, s2>>>(idx);
    cudaEventRecord(evJoin, s2);

    // GEMM arm on main, chunked
    k_pre<<<65, 256>>>(Wq, bq, Wk, bk);
    k_z<<<QSPLIT / ZT, 256>>>(queries, 0);                       // chunk0: q in [0, QSPLIT)
    cudaEventRecord(evZ0, 0);
    k_z<<<(QN - QSPLIT + ZT - 1) / ZT, 256>>>(queries, QSPLIT);  // chunk1

    // fused chunk0 on s3 (overlaps kz chunk1 on main)
    cudaStreamWaitEvent(s3, evZ0, 0);
    cudaStreamWaitEvent(s3, evJoin, 0);
    k_fused<<<QSPLIT / 8, 256, 0, s3>>>(sv, scores, attn, 0);
    cudaEventRecord(evF0, s3);

    // fused chunk1 on main, then join s3 back
    cudaStreamWaitEvent(0, evJoin, 0);
    k_fused<<<(QN - QSPLIT + 7) / 8, 256>>>(sv, scores, attn, QSPLIT);
    cudaStreamWaitEvent(0, evF0, 0);
}